// round 1
// baseline (speedup 1.0000x reference)
#include <cuda_runtime.h>
#include <math.h>

#define T_TOK 32768
#define DIM   128
#define KC    8192
#define BM    128
#define BN    128
#define PAD   132
#define SMEM_BYTES (2 * DIM * PAD * 4)

// ---- device scratch (no allocations allowed) ----
__device__ float  g_codebook[KC * DIM];
__device__ float  g_cnorm[KC];
__device__ int    g_idx[T_TOK];
__device__ int    g_counts[KC];
__device__ double g_sse;

// ---- zero accumulators ----
__global__ void k_init() {
    int i = blockIdx.x * blockDim.x + threadIdx.x;
    if (i < KC) g_counts[i] = 0;
    if (i == 0) g_sse = 0.0;
}

// ---- codebook projection: C[k][d] = sum_j emb[k][j]*pw[d][j] + pb[d]; cnorm[k]=|C_k|^2 ----
__global__ void k_proj(const float* __restrict__ emb,
                       const float* __restrict__ pw,
                       const float* __restrict__ pb) {
    __shared__ float e[DIM];
    __shared__ float ws[4];
    int k = blockIdx.x, d = threadIdx.x;
    e[d] = emb[k * DIM + d];
    __syncthreads();
    const float* w = pw + d * DIM;
    float acc = pb[d];
#pragma unroll
    for (int j = 0; j < DIM; j++) acc = fmaf(e[j], w[j], acc);
    g_codebook[k * DIM + d] = acc;
    float s = acc * acc;
#pragma unroll
    for (int o = 16; o > 0; o >>= 1) s += __shfl_down_sync(0xffffffffu, s, o);
    if ((d & 31) == 0) ws[d >> 5] = s;
    __syncthreads();
    if (d == 0) g_cnorm[k] = ws[0] + ws[1] + ws[2] + ws[3];
}

// ---- fused distance GEMM + argmin ----
// score(t,k) = cnorm[k] - 2 * z_t . c_k   (|z|^2 dropped: constant per row)
// Block: BM=128 tokens x all K codes (BN=128 per iter), 256 threads, 8x8 reg tile.
// Smem tiles stored d-major (transposed) with XOR swizzle on m-block + pad 132.
__global__ __launch_bounds__(256, 1)
void k_argmin(const float* __restrict__ z) {
    extern __shared__ float smem[];
    float* zs = smem;             // [DIM][PAD]
    float* cs = smem + DIM * PAD; // [DIM][PAD]
    const int tid = threadIdx.x;
    const int tx = tid & 15, ty = tid >> 4;
    const int m0 = blockIdx.x * BM;

    // load z tile: global [m][d] -> smem [d][m] (swizzled)
#pragma unroll
    for (int i = 0; i < 16; i++) {
        int f  = tid + i * 256;
        int m  = f >> 5;
        int c4 = f & 31;
        float4 v = *((const float4*)(z + (size_t)(m0 + m) * DIM) + c4);
        int sw = (((m >> 2) ^ (c4 & 7)) << 2) | (m & 3);
        zs[(4 * c4 + 0) * PAD + sw] = v.x;
        zs[(4 * c4 + 1) * PAD + sw] = v.y;
        zs[(4 * c4 + 2) * PAD + sw] = v.z;
        zs[(4 * c4 + 3) * PAD + sw] = v.w;
    }

    float best[8];
    int   bidx[8];
#pragma unroll
    for (int i = 0; i < 8; i++) { best[i] = 3.4e38f; bidx[i] = 0; }

    for (int n0 = 0; n0 < KC; n0 += BN) {
        __syncthreads();
        // load C tile: global [n][d] -> smem [d][n] (swizzled)
#pragma unroll
        for (int i = 0; i < 16; i++) {
            int f  = tid + i * 256;
            int n  = f >> 5;
            int c4 = f & 31;
            float4 v = *((const float4*)(g_codebook + (size_t)(n0 + n) * DIM) + c4);
            int sw = (((n >> 2) ^ (c4 & 7)) << 2) | (n & 3);
            cs[(4 * c4 + 0) * PAD + sw] = v.x;
            cs[(4 * c4 + 1) * PAD + sw] = v.y;
            cs[(4 * c4 + 2) * PAD + sw] = v.z;
            cs[(4 * c4 + 3) * PAD + sw] = v.w;
        }
        __syncthreads();

        float acc[8][8];
#pragma unroll
        for (int im = 0; im < 8; im++)
#pragma unroll
            for (int jn = 0; jn < 8; jn++) acc[im][jn] = 0.0f;

#pragma unroll 4
        for (int d = 0; d < DIM; d++) {
            int s = (d >> 2) & 7;
            const float* zr = zs + d * PAD;
            const float* cr = cs + d * PAD;
            float4 a0 = *(const float4*)(zr + ((ty ^ s) << 2));
            float4 a1 = *(const float4*)(zr + 64 + ((ty ^ s) << 2));
            float4 b0 = *(const float4*)(cr + ((tx ^ s) << 2));
            float4 b1 = *(const float4*)(cr + 64 + ((tx ^ s) << 2));
            float a[8] = {a0.x, a0.y, a0.z, a0.w, a1.x, a1.y, a1.z, a1.w};
            float b[8] = {b0.x, b0.y, b0.z, b0.w, b1.x, b1.y, b1.z, b1.w};
#pragma unroll
            for (int im = 0; im < 8; im++)
#pragma unroll
                for (int jn = 0; jn < 8; jn++)
                    acc[im][jn] = fmaf(a[im], b[jn], acc[im][jn]);
        }

        // fold into running argmin
#pragma unroll
        for (int jn = 0; jn < 8; jn++) {
            int n = n0 + ((jn < 4) ? (tx * 4 + jn) : (64 + tx * 4 + jn - 4));
            float cn = g_cnorm[n];
#pragma unroll
            for (int im = 0; im < 8; im++) {
                float v = fmaf(-2.0f, acc[im][jn], cn);
                if (v < best[im]) { best[im] = v; bidx[im] = n; }
                else if (v == best[im] && n < bidx[im]) { bidx[im] = n; }
            }
        }
    }

    // reduce argmin across the 16 tx lanes sharing each token row
#pragma unroll
    for (int im = 0; im < 8; im++) {
        float v = best[im];
        int   ix = bidx[im];
#pragma unroll
        for (int off = 8; off > 0; off >>= 1) {
            float ov = __shfl_down_sync(0xffffffffu, v, off, 16);
            int   oi = __shfl_down_sync(0xffffffffu, ix, off, 16);
            if (ov < v || (ov == v && oi < ix)) { v = ov; ix = oi; }
        }
        if (tx == 0) {
            int m = (im < 4) ? (ty * 4 + im) : (64 + ty * 4 + im - 4);
            g_idx[m0 + m] = ix;
        }
    }
}

// ---- gather z_q, accumulate SSE and counts ----
__global__ void k_gather(const float* __restrict__ z, float* __restrict__ out) {
    int gid = blockIdx.x * 256 + threadIdx.x;
    int t = gid >> 7;
    int d = gid & 127;
    int ix = g_idx[t];
    float zv = z[gid];
    float c  = g_codebook[(size_t)ix * DIM + d];
    out[gid] = zv + (c - zv);   // straight-through value == z_q
    float df = c - zv;
    float sq = df * df;
#pragma unroll
    for (int o = 16; o > 0; o >>= 1) sq += __shfl_down_sync(0xffffffffu, sq, o);
    __shared__ float ws[8];
    if ((threadIdx.x & 31) == 0) ws[threadIdx.x >> 5] = sq;
    __syncthreads();
    if (threadIdx.x == 0) {
        float ssum = 0.0f;
#pragma unroll
        for (int i = 0; i < 8; i++) ssum += ws[i];
        atomicAdd(&g_sse, (double)ssum);
    }
    if (d == 0) atomicAdd(&g_counts[ix], 1);
}

// ---- finalize commit_loss + perplexity ----
__global__ void k_final(float* __restrict__ out) {
    __shared__ float ws[8];
    float s = 0.0f;
    const float invT = 1.0f / (float)T_TOK;
    for (int i = threadIdx.x; i < KC; i += 256) {
        float e = (float)g_counts[i] * invT;
        s += e * logf(e + 1e-8f);
    }
#pragma unroll
    for (int o = 16; o > 0; o >>= 1) s += __shfl_down_sync(0xffffffffu, s, o);
    if ((threadIdx.x & 31) == 0) ws[threadIdx.x >> 5] = s;
    __syncthreads();
    if (threadIdx.x == 0) {
        float tot = 0.0f;
#pragma unroll
        for (int i = 0; i < 8; i++) tot += ws[i];
        double mse = g_sse / (double)((size_t)T_TOK * DIM);
        out[(size_t)T_TOK * DIM]     = (float)(1.25 * mse);   // (1 + BETA) * mean
        out[(size_t)T_TOK * DIM + 1] = expf(-tot);
    }
}

extern "C" void kernel_launch(void* const* d_in, const int* in_sizes, int n_in,
                              void* d_out, int out_size) {
    const float* z   = (const float*)d_in[0];
    const float* emb = (const float*)d_in[1];
    const float* pw  = (const float*)d_in[2];
    const float* pb  = (const float*)d_in[3];
    float* out = (float*)d_out;

    cudaFuncSetAttribute(k_argmin, cudaFuncAttributeMaxDynamicSharedMemorySize, SMEM_BYTES);

    k_init<<<(KC + 255) / 256, 256>>>();
    k_proj<<<KC, DIM>>>(emb, pw, pb);
    k_argmin<<<T_TOK / BM, 256, SMEM_BYTES>>>(z);
    k_gather<<<(T_TOK * DIM) / 256, 256>>>(z, out);
    k_final<<<1, 256>>>(out);
}

// round 2
// speedup vs baseline: 1.0004x; 1.0004x over previous
#include <cuda_runtime.h>
#include <math.h>

#define T_TOK 32768
#define DIM   128
#define KC    8192
#define BM    128
#define BN    128
#define PAD   132
#define SMEM_BYTES (2 * DIM * PAD * 4)

// ---- device scratch (no allocations allowed) ----
__device__ float  g_codebook[KC * DIM];
__device__ float  g_cnorm[KC];
__device__ int    g_idx[T_TOK];
__device__ int    g_counts[KC];
__device__ double g_sse;

// ---- zero accumulators ----
__global__ void k_init() {
    int i = blockIdx.x * blockDim.x + threadIdx.x;
    if (i < KC) g_counts[i] = 0;
    if (i == 0) g_sse = 0.0;
}

// ---- codebook projection: C[k][d] = sum_j emb[k][j]*pw[d][j] + pb[d]; cnorm[k]=|C_k|^2 ----
__global__ void k_proj(const float* __restrict__ emb,
                       const float* __restrict__ pw,
                       const float* __restrict__ pb) {
    __shared__ float e[DIM];
    __shared__ float ws[4];
    int k = blockIdx.x, d = threadIdx.x;
    e[d] = emb[k * DIM + d];
    __syncthreads();
    const float* w = pw + d * DIM;
    float acc = pb[d];
#pragma unroll
    for (int j = 0; j < DIM; j++) acc = fmaf(e[j], w[j], acc);
    g_codebook[k * DIM + d] = acc;
    float s = acc * acc;
#pragma unroll
    for (int o = 16; o > 0; o >>= 1) s += __shfl_down_sync(0xffffffffu, s, o);
    if ((d & 31) == 0) ws[d >> 5] = s;
    __syncthreads();
    if (d == 0) g_cnorm[k] = ws[0] + ws[1] + ws[2] + ws[3];
}

// ---- fused distance GEMM + argmin ----
// score(t,k) = cnorm[k] - 2 * z_t . c_k   (|z|^2 dropped: constant per row)
// Block: BM=128 tokens x all K codes (BN=128 per iter), 256 threads, 8x8 reg tile.
// Smem tiles stored d-major (transposed) with XOR swizzle on m-block + pad 132.
__global__ __launch_bounds__(256, 1)
void k_argmin(const float* __restrict__ z) {
    extern __shared__ float smem[];
    float* zs = smem;             // [DIM][PAD]
    float* cs = smem + DIM * PAD; // [DIM][PAD]
    const int tid = threadIdx.x;
    const int tx = tid & 15, ty = tid >> 4;
    const int m0 = blockIdx.x * BM;

    // load z tile: global [m][d] -> smem [d][m] (swizzled)
#pragma unroll
    for (int i = 0; i < 16; i++) {
        int f  = tid + i * 256;
        int m  = f >> 5;
        int c4 = f & 31;
        float4 v = *((const float4*)(z + (size_t)(m0 + m) * DIM) + c4);
        int sw = (((m >> 2) ^ (c4 & 7)) << 2) | (m & 3);
        zs[(4 * c4 + 0) * PAD + sw] = v.x;
        zs[(4 * c4 + 1) * PAD + sw] = v.y;
        zs[(4 * c4 + 2) * PAD + sw] = v.z;
        zs[(4 * c4 + 3) * PAD + sw] = v.w;
    }

    float best[8];
    int   bidx[8];
#pragma unroll
    for (int i = 0; i < 8; i++) { best[i] = 3.4e38f; bidx[i] = 0; }

    for (int n0 = 0; n0 < KC; n0 += BN) {
        __syncthreads();
        // load C tile: global [n][d] -> smem [d][n] (swizzled)
#pragma unroll
        for (int i = 0; i < 16; i++) {
            int f  = tid + i * 256;
            int n  = f >> 5;
            int c4 = f & 31;
            float4 v = *((const float4*)(g_codebook + (size_t)(n0 + n) * DIM) + c4);
            int sw = (((n >> 2) ^ (c4 & 7)) << 2) | (n & 3);
            cs[(4 * c4 + 0) * PAD + sw] = v.x;
            cs[(4 * c4 + 1) * PAD + sw] = v.y;
            cs[(4 * c4 + 2) * PAD + sw] = v.z;
            cs[(4 * c4 + 3) * PAD + sw] = v.w;
        }
        __syncthreads();

        float acc[8][8];
#pragma unroll
        for (int im = 0; im < 8; im++)
#pragma unroll
            for (int jn = 0; jn < 8; jn++) acc[im][jn] = 0.0f;

#pragma unroll 4
        for (int d = 0; d < DIM; d++) {
            int s = (d >> 2) & 7;
            const float* zr = zs + d * PAD;
            const float* cr = cs + d * PAD;
            float4 a0 = *(const float4*)(zr + ((ty ^ s) << 2));
            float4 a1 = *(const float4*)(zr + 64 + ((ty ^ s) << 2));
            float4 b0 = *(const float4*)(cr + ((tx ^ s) << 2));
            float4 b1 = *(const float4*)(cr + 64 + ((tx ^ s) << 2));
            float a[8] = {a0.x, a0.y, a0.z, a0.w, a1.x, a1.y, a1.z, a1.w};
            float b[8] = {b0.x, b0.y, b0.z, b0.w, b1.x, b1.y, b1.z, b1.w};
#pragma unroll
            for (int im = 0; im < 8; im++)
#pragma unroll
                for (int jn = 0; jn < 8; jn++)
                    acc[im][jn] = fmaf(a[im], b[jn], acc[im][jn]);
        }

        // fold into running argmin
#pragma unroll
        for (int jn = 0; jn < 8; jn++) {
            int n = n0 + ((jn < 4) ? (tx * 4 + jn) : (64 + tx * 4 + jn - 4));
            float cn = g_cnorm[n];
#pragma unroll
            for (int im = 0; im < 8; im++) {
                float v = fmaf(-2.0f, acc[im][jn], cn);
                if (v < best[im]) { best[im] = v; bidx[im] = n; }
                else if (v == best[im] && n < bidx[im]) { bidx[im] = n; }
            }
        }
    }

    // reduce argmin across the 16 tx lanes sharing each token row
#pragma unroll
    for (int im = 0; im < 8; im++) {
        float v = best[im];
        int   ix = bidx[im];
#pragma unroll
        for (int off = 8; off > 0; off >>= 1) {
            float ov = __shfl_down_sync(0xffffffffu, v, off, 16);
            int   oi = __shfl_down_sync(0xffffffffu, ix, off, 16);
            if (ov < v || (ov == v && oi < ix)) { v = ov; ix = oi; }
        }
        if (tx == 0) {
            int m = (im < 4) ? (ty * 4 + im) : (64 + ty * 4 + im - 4);
            g_idx[m0 + m] = ix;
        }
    }
}

// ---- gather z_q, accumulate SSE and counts ----
__global__ void k_gather(const float* __restrict__ z, float* __restrict__ out) {
    int gid = blockIdx.x * 256 + threadIdx.x;
    int t = gid >> 7;
    int d = gid & 127;
    int ix = g_idx[t];
    float zv = z[gid];
    float c  = g_codebook[(size_t)ix * DIM + d];
    out[gid] = zv + (c - zv);   // straight-through value == z_q
    float df = c - zv;
    float sq = df * df;
#pragma unroll
    for (int o = 16; o > 0; o >>= 1) sq += __shfl_down_sync(0xffffffffu, sq, o);
    __shared__ float ws[8];
    if ((threadIdx.x & 31) == 0) ws[threadIdx.x >> 5] = sq;
    __syncthreads();
    if (threadIdx.x == 0) {
        float ssum = 0.0f;
#pragma unroll
        for (int i = 0; i < 8; i++) ssum += ws[i];
        atomicAdd(&g_sse, (double)ssum);
    }
    if (d == 0) atomicAdd(&g_counts[ix], 1);
}

// ---- finalize commit_loss + perplexity ----
__global__ void k_final(float* __restrict__ out) {
    __shared__ float ws[8];
    float s = 0.0f;
    const float invT = 1.0f / (float)T_TOK;
    for (int i = threadIdx.x; i < KC; i += 256) {
        float e = (float)g_counts[i] * invT;
        s += e * logf(e + 1e-8f);
    }
#pragma unroll
    for (int o = 16; o > 0; o >>= 1) s += __shfl_down_sync(0xffffffffu, s, o);
    if ((threadIdx.x & 31) == 0) ws[threadIdx.x >> 5] = s;
    __syncthreads();
    if (threadIdx.x == 0) {
        float tot = 0.0f;
#pragma unroll
        for (int i = 0; i < 8; i++) tot += ws[i];
        double mse = g_sse / (double)((size_t)T_TOK * DIM);
        out[(size_t)T_TOK * DIM]     = (float)(1.25 * mse);   // (1 + BETA) * mean
        out[(size_t)T_TOK * DIM + 1] = expf(-tot);
    }
}

extern "C" void kernel_launch(void* const* d_in, const int* in_sizes, int n_in,
                              void* d_out, int out_size) {
    const float* z   = (const float*)d_in[0];
    const float* emb = (const float*)d_in[1];
    const float* pw  = (const float*)d_in[2];
    const float* pb  = (const float*)d_in[3];
    float* out = (float*)d_out;

    cudaFuncSetAttribute(k_argmin, cudaFuncAttributeMaxDynamicSharedMemorySize, SMEM_BYTES);

    k_init<<<(KC + 255) / 256, 256>>>();
    k_proj<<<KC, DIM>>>(emb, pw, pb);
    k_argmin<<<T_TOK / BM, 256, SMEM_BYTES>>>(z);
    k_gather<<<(T_TOK * DIM) / 256, 256>>>(z, out);
    k_final<<<1, 256>>>(out);
}

// round 4
// speedup vs baseline: 2.0744x; 2.0735x over previous
#include <cuda_runtime.h>
#include <cuda_bf16.h>
#include <math.h>
#include <stdint.h>

#define T_TOK 32768
#define DIM   128
#define KC    8192
#define BM    128
#define NT    64
#define ITERS (KC / NT)          /* 128 */
#define GRID_GEMM (T_TOK / BM)   /* 256 */
#define TILE_BYTES 32768
#define SMEM_GEMM (2 * TILE_BYTES)

/* ---------------- device scratch (no allocations) ---------------- */
__device__ __align__(16) unsigned char g_cbt[ITERS * TILE_BYTES]; /* 4MB packed B frags */
__device__ float  g_codebook[KC * DIM];
__device__ __align__(16) float g_cnorm[KC];
__device__ int2   g_cand[T_TOK];
__device__ int    g_counts[KC];
__device__ double g_ssep[T_TOK / 8];

__device__ __forceinline__ uint32_t smem_u32(const void* p) {
    uint32_t a;
    asm("{ .reg .u64 t; cvta.to.shared.u64 t, %1; cvt.u32.u64 %0, t; }"
        : "=r"(a) : "l"(p));
    return a;
}

#define CP16(dst, src) \
    asm volatile("cp.async.cg.shared.global [%0], [%1], 16;" :: "r"((uint32_t)(dst)), "l"(src))
#define CP_COMMIT() asm volatile("cp.async.commit_group;" ::: "memory")
#define CP_WAIT0()  asm volatile("cp.async.wait_group 0;"  ::: "memory")

#define MMA_BF16(d, a, b0, b1) \
    asm volatile("mma.sync.aligned.m16n8k16.row.col.f32.bf16.bf16.f32 " \
                 "{%0,%1,%2,%3}, {%4,%5,%6,%7}, {%8,%9}, {%0,%1,%2,%3};" \
                 : "+f"((d)[0]), "+f"((d)[1]), "+f"((d)[2]), "+f"((d)[3]) \
                 : "r"((a)[0]), "r"((a)[1]), "r"((a)[2]), "r"((a)[3]), \
                   "r"(b0), "r"(b1))

#define TOP2(v1, i1, v2, i2, v, n) do {                         \
    if ((v) < (v2)) {                                           \
        if ((v) < (v1)) { v2 = v1; i2 = i1; v1 = (v); i1 = (n); } \
        else            { v2 = (v); i2 = (n); }                 \
    }                                                           \
} while (0)

/* ---------------- zero counts ---------------- */
__global__ void k_init() {
    int i = blockIdx.x * blockDim.x + threadIdx.x;
    if (i < KC) g_counts[i] = 0;
}

/* ---------------- projection: C = emb @ W^T + b; cnorm; pack bf16 hi/lo B-fragments ---------------- */
/* packed layout per 64-code tile (32KB):
   [nblk(8)][kblk(8)][reg(2)][lane(32)] x 8B, 8B = {hi_k, hi_k+1, lo_k, lo_k+1}
   where lane = nl*4 + ksub, n = tile*64 + nblk*8 + nl, k = kblk*16 + reg*8 + ksub*2 */
__global__ void k_proj(const float* __restrict__ emb,
                       const float* __restrict__ pw,
                       const float* __restrict__ pb) {
    __shared__ float e[DIM];
    __shared__ float ws[4];
    int c = blockIdx.x, d = threadIdx.x;
    e[d] = emb[c * DIM + d];
    __syncthreads();
    const float* w = pw + d * DIM;
    float acc = pb[d];
#pragma unroll
    for (int j = 0; j < DIM; j++) acc = fmaf(e[j], w[j], acc);
    g_codebook[c * DIM + d] = acc;

    __nv_bfloat16 h = __float2bfloat16(acc);
    float rlo = acc - __bfloat162float(h);
    __nv_bfloat16 l = __float2bfloat16(rlo);

    int tile = c >> 6, nblk = (c >> 3) & 7, nl = c & 7;
    int kblk = d >> 4, reg = (d >> 3) & 1, ksub = (d >> 1) & 3, par = d & 1;
    int lane = nl * 4 + ksub;
    size_t base = (size_t)tile * TILE_BYTES + nblk * 4096 + kblk * 512 + reg * 256 + lane * 8;
    *(__nv_bfloat16*)(g_cbt + base + par * 2)     = h;
    *(__nv_bfloat16*)(g_cbt + base + 4 + par * 2) = l;

    float s = acc * acc;
#pragma unroll
    for (int o = 16; o > 0; o >>= 1) s += __shfl_down_sync(0xffffffffu, s, o);
    if ((d & 31) == 0) ws[d >> 5] = s;
    __syncthreads();
    if (d == 0) g_cnorm[c] = ws[0] + ws[1] + ws[2] + ws[3];
}

/* ---------------- fused HMMA distance GEMM + top-2 argmin ---------------- */
__global__ __launch_bounds__(256, 1)
void k_gemm(const float* __restrict__ z) {
    extern __shared__ unsigned char smem[];
    const uint32_t sb = smem_u32(smem);
    const int tid = threadIdx.x;
    const int lane = tid & 31;
    const int warp = tid >> 5;
    const int r = lane >> 2;       /* row within m16 */
    const int cc = lane & 3;       /* col group */
    const int m0 = blockIdx.x * BM;

    /* prologue: start copy of B tile 0 */
#pragma unroll
    for (int j = 0; j < 8; j++) {
        uint32_t off = (uint32_t)(tid + j * 256) * 16;
        CP16(sb + off, g_cbt + off);
    }
    CP_COMMIT();

    /* A fragments (hi/lo) in registers: warp owns rows m0+warp*16 .. +15 */
    uint32_t Ah[8][4], Al[8][4];
    {
        const float* z0 = z + (size_t)(m0 + warp * 16 + r) * DIM;
#pragma unroll
        for (int kb = 0; kb < 8; kb++) {
#pragma unroll
            for (int q = 0; q < 4; q++) {
                const float* src = z0 + ((q & 1) ? 8 * DIM : 0) + kb * 16 + (q >> 1) * 8 + cc * 2;
                float2 v = *(const float2*)src;
                __nv_bfloat162 hh = __floats2bfloat162_rn(v.x, v.y);
                float lx = v.x - __bfloat162float(__low2bfloat16(hh));
                float ly = v.y - __bfloat162float(__high2bfloat16(hh));
                __nv_bfloat162 ll = __floats2bfloat162_rn(lx, ly);
                Ah[kb][q] = *(uint32_t*)&hh;
                Al[kb][q] = *(uint32_t*)&ll;
            }
        }
    }

    float v1a = 3.4e38f, v2a = 3.4e38f, v1b = 3.4e38f, v2b = 3.4e38f;
    int   i1a = 0, i2a = 0, i1b = 0, i2b = 0;

    for (int i = 0; i < ITERS; i++) {
        CP_WAIT0();
        __syncthreads();
        if (i + 1 < ITERS) {
            const unsigned char* src = g_cbt + (size_t)(i + 1) * TILE_BYTES;
            uint32_t dst = sb + ((i + 1) & 1) * TILE_BYTES;
#pragma unroll
            for (int j = 0; j < 8; j++) {
                uint32_t off = (uint32_t)(tid + j * 256) * 16;
                CP16(dst + off, src + off);
            }
            CP_COMMIT();
        }

        float acc[8][4];
#pragma unroll
        for (int nb = 0; nb < 8; nb++)
#pragma unroll
            for (int q = 0; q < 4; q++) acc[nb][q] = 0.0f;

        const uint32_t bbase = sb + (i & 1) * TILE_BYTES + lane * 8;
#pragma unroll
        for (int kb = 0; kb < 8; kb++) {
#pragma unroll
            for (int nb = 0; nb < 8; nb++) {
                uint32_t addr = bbase + nb * 4096 + kb * 512;
                uint32_t bh0, bl0, bh1, bl1;
                asm volatile("ld.shared.v2.b32 {%0,%1},[%2];" : "=r"(bh0), "=r"(bl0) : "r"(addr));
                asm volatile("ld.shared.v2.b32 {%0,%1},[%2];" : "=r"(bh1), "=r"(bl1) : "r"(addr + 256));
                MMA_BF16(acc[nb], Ah[kb], bh0, bh1);
                MMA_BF16(acc[nb], Ah[kb], bl0, bl1);
                MMA_BF16(acc[nb], Al[kb], bh0, bh1);
            }
        }

        const int n0i = i * 64;
#pragma unroll
        for (int nb = 0; nb < 8; nb++) {
            int n = n0i + nb * 8 + cc * 2;
            float2 cn = *(const float2*)(g_cnorm + n);
            float s0 = fmaf(-2.0f, acc[nb][0], cn.x);
            float s1 = fmaf(-2.0f, acc[nb][1], cn.y);
            float s2 = fmaf(-2.0f, acc[nb][2], cn.x);
            float s3 = fmaf(-2.0f, acc[nb][3], cn.y);
            TOP2(v1a, i1a, v2a, i2a, s0, n);
            TOP2(v1a, i1a, v2a, i2a, s1, n + 1);
            TOP2(v1b, i1b, v2b, i2b, s2, n);
            TOP2(v1b, i1b, v2b, i2b, s3, n + 1);
        }
    }

    /* merge top-2 across the 4 lanes of each row group */
#pragma unroll
    for (int off = 1; off <= 2; off <<= 1) {
        float w1, w2; int j1, j2;
        w1 = __shfl_xor_sync(0xffffffffu, v1a, off);
        j1 = __shfl_xor_sync(0xffffffffu, i1a, off);
        w2 = __shfl_xor_sync(0xffffffffu, v2a, off);
        j2 = __shfl_xor_sync(0xffffffffu, i2a, off);
        {
            bool wb = (w1 < v1a) || (w1 == v1a && j1 < i1a);
            float t1 = wb ? w1 : v1a; int ti1 = wb ? j1 : i1a;
            float lv = wb ? v1a : w1; int li = wb ? i1a : j1;
            float sv = wb ? w2 : v2a; int si = wb ? j2 : i2a;
            bool sb2 = (lv < sv) || (lv == sv && li < si);
            v1a = t1; i1a = ti1; v2a = sb2 ? lv : sv; i2a = sb2 ? li : si;
        }
        w1 = __shfl_xor_sync(0xffffffffu, v1b, off);
        j1 = __shfl_xor_sync(0xffffffffu, i1b, off);
        w2 = __shfl_xor_sync(0xffffffffu, v2b, off);
        j2 = __shfl_xor_sync(0xffffffffu, i2b, off);
        {
            bool wb = (w1 < v1b) || (w1 == v1b && j1 < i1b);
            float t1 = wb ? w1 : v1b; int ti1 = wb ? j1 : i1b;
            float lv = wb ? v1b : w1; int li = wb ? i1b : j1;
            float sv = wb ? w2 : v2b; int si = wb ? j2 : i2b;
            bool sb2 = (lv < sv) || (lv == sv && li < si);
            v1b = t1; i1b = ti1; v2b = sb2 ? lv : sv; i2b = sb2 ? li : si;
        }
    }
    if (cc == 0) {
        int tok = m0 + warp * 16 + r;
        g_cand[tok]     = make_int2(i1a, i2a);
        g_cand[tok + 8] = make_int2(i1b, i2b);
    }
}

/* ---------------- exact rescore of top-2 + gather + loss partials ---------------- */
__global__ __launch_bounds__(256)
void k_rescore(const float* __restrict__ z, float* __restrict__ out) {
    __shared__ float wsq[8];
    const int lane = threadIdx.x & 31;
    const int warp = threadIdx.x >> 5;
    const int t = blockIdx.x * 8 + warp;

    int2 cd = g_cand[t];
    float4 zv = ((const float4*)(z + (size_t)t * DIM))[lane];
    float4 c1 = ((const float4*)(g_codebook + (size_t)cd.x * DIM))[lane];
    float4 c2 = ((const float4*)(g_codebook + (size_t)cd.y * DIM))[lane];
    float d1 = zv.x * c1.x + zv.y * c1.y + zv.z * c1.z + zv.w * c1.w;
    float d2 = zv.x * c2.x + zv.y * c2.y + zv.z * c2.z + zv.w * c2.w;
#pragma unroll
    for (int o = 16; o > 0; o >>= 1) {
        d1 += __shfl_xor_sync(0xffffffffu, d1, o);
        d2 += __shfl_xor_sync(0xffffffffu, d2, o);
    }
    float s1 = g_cnorm[cd.x] - 2.0f * d1;
    float s2 = g_cnorm[cd.y] - 2.0f * d2;
    bool take2 = (s2 < s1) || (s2 == s1 && cd.y < cd.x);
    int idx = take2 ? cd.y : cd.x;
    float4 c = take2 ? c2 : c1;

    float dx = c.x - zv.x, dy = c.y - zv.y, dz = c.z - zv.z, dw = c.w - zv.w;
    float4 o4;
    o4.x = zv.x + dx; o4.y = zv.y + dy; o4.z = zv.z + dz; o4.w = zv.w + dw;
    ((float4*)(out + (size_t)t * DIM))[lane] = o4;

    float sq = dx * dx + dy * dy + dz * dz + dw * dw;
#pragma unroll
    for (int o = 16; o > 0; o >>= 1) sq += __shfl_xor_sync(0xffffffffu, sq, o);
    if (lane == 0) {
        wsq[warp] = sq;
        atomicAdd(&g_counts[idx], 1);
    }
    __syncthreads();
    if (threadIdx.x == 0) {
        double s = 0.0;
#pragma unroll
        for (int i = 0; i < 8; i++) s += (double)wsq[i];
        g_ssep[blockIdx.x] = s;
    }
}

/* ---------------- finalize commit_loss + perplexity ---------------- */
__global__ void k_final(float* __restrict__ out) {
    __shared__ double wd[8];
    __shared__ float wf[8];
    double sd = 0.0;
    for (int j = threadIdx.x; j < T_TOK / 8; j += 256) sd += g_ssep[j];
    float s = 0.0f;
    const float invT = 1.0f / (float)T_TOK;
    for (int i = threadIdx.x; i < KC; i += 256) {
        float e = (float)g_counts[i] * invT;
        s += e * logf(e + 1e-8f);
    }
#pragma unroll
    for (int o = 16; o > 0; o >>= 1) {
        sd += __shfl_down_sync(0xffffffffu, sd, o);
        s  += __shfl_down_sync(0xffffffffu, s, o);
    }
    if ((threadIdx.x & 31) == 0) { wd[threadIdx.x >> 5] = sd; wf[threadIdx.x >> 5] = s; }
    __syncthreads();
    if (threadIdx.x == 0) {
        double td = 0.0; float tf = 0.0f;
#pragma unroll
        for (int i = 0; i < 8; i++) { td += wd[i]; tf += wf[i]; }
        double mse = td / (double)((size_t)T_TOK * DIM);
        out[(size_t)T_TOK * DIM]     = (float)(1.25 * mse);
        out[(size_t)T_TOK * DIM + 1] = expf(-tf);
    }
}

extern "C" void kernel_launch(void* const* d_in, const int* in_sizes, int n_in,
                              void* d_out, int out_size) {
    const float* z   = (const float*)d_in[0];
    const float* emb = (const float*)d_in[1];
    const float* pw  = (const float*)d_in[2];
    const float* pb  = (const float*)d_in[3];
    float* out = (float*)d_out;

    cudaFuncSetAttribute(k_gemm, cudaFuncAttributeMaxDynamicSharedMemorySize, SMEM_GEMM);

    k_init<<<KC / 256, 256>>>();
    k_proj<<<KC, DIM>>>(emb, pw, pb);
    k_gemm<<<GRID_GEMM, 256, SMEM_GEMM>>>(z);
    k_rescore<<<T_TOK / 8, 256>>>(z, out);
    k_final<<<1, 256>>>(out);
}

// round 5
// speedup vs baseline: 6.7897x; 3.2732x over previous
#include <cuda_runtime.h>
#include <cuda_fp16.h>
#include <math.h>
#include <stdint.h>

#define T_TOK 32768
#define DIM   128
#define KC    8192
#define BM    128
#define NT    64
#define ITERS (KC / NT)          /* 128 */
#define GRID_GEMM (T_TOK / BM)   /* 256 */
#define TILE_BYTES 16384
#define SMEM_GEMM (2 * TILE_BYTES)
#define PAD 132
#define SMEM_PROJ (2 * 128 * PAD * 4)

/* ---------------- device scratch (no allocations) ---------------- */
__device__ __align__(16) unsigned char g_cbt[ITERS * TILE_BYTES]; /* 2MB fp16 B frags */
__device__ float  g_codebook[KC * DIM];
__device__ __align__(16) float g_cnorm[KC];
__device__ int4   g_cand[T_TOK];
__device__ int    g_counts[KC];
__device__ double g_ssep[T_TOK / 8];

__device__ __forceinline__ uint32_t smem_u32(const void* p) {
    uint32_t a;
    asm("{ .reg .u64 t; cvta.to.shared.u64 t, %1; cvt.u32.u64 %0, t; }"
        : "=r"(a) : "l"(p));
    return a;
}

#define CP16(dst, src) \
    asm volatile("cp.async.cg.shared.global [%0], [%1], 16;" :: "r"((uint32_t)(dst)), "l"(src))
#define CP_COMMIT() asm volatile("cp.async.commit_group;" ::: "memory")
#define CP_WAIT0()  asm volatile("cp.async.wait_group 0;"  ::: "memory")

#define MMA_F16(d, a, b0, b1) \
    asm volatile("mma.sync.aligned.m16n8k16.row.col.f32.f16.f16.f32 " \
                 "{%0,%1,%2,%3}, {%4,%5,%6,%7}, {%8,%9}, {%0,%1,%2,%3};" \
                 : "+f"((d)[0]), "+f"((d)[1]), "+f"((d)[2]), "+f"((d)[3]) \
                 : "r"((a)[0]), "r"((a)[1]), "r"((a)[2]), "r"((a)[3]), \
                   "r"(b0), "r"(b1))

#define INS4(tv0, tv1, tv2, tv3, ti0, ti1, ti2, ti3, v, n) do {               \
    if ((v) < (tv3)) {                                                        \
        if ((v) < (tv2)) {                                                    \
            tv3 = tv2; ti3 = ti2;                                             \
            if ((v) < (tv1)) {                                                \
                tv2 = tv1; ti2 = ti1;                                         \
                if ((v) < (tv0)) { tv1 = tv0; ti1 = ti0; tv0 = (v); ti0 = (n); } \
                else             { tv1 = (v); ti1 = (n); }                    \
            } else { tv2 = (v); ti2 = (n); }                                  \
        } else { tv3 = (v); ti3 = (n); }                                      \
    }                                                                         \
} while (0)

/* ---------------- zero counts ---------------- */
__global__ void k_init() {
    int i = blockIdx.x * blockDim.x + threadIdx.x;
    if (i < KC) g_counts[i] = 0;
}

/* ---------------- projection GEMM: C = emb @ W^T + b (128 codes/block, register tiled) ----------------
   Also emits: fp32 codebook, cnorm, fp16 packed B fragments for the distance GEMM.
   Packed layout per 64-code tile (16KB): [nblk(8)][kblk(8)][lane(32)] x 8B,
   8B = {h(k), h(k+1), h(k+8), h(k+9)}, lane = nl*4 + ksub,
   n = tile*64 + nblk*8 + nl, k = kblk*16 + regsel*8 + ksub*2 + par */
__global__ __launch_bounds__(256, 1)
void k_proj(const float* __restrict__ emb,
            const float* __restrict__ pw,
            const float* __restrict__ pbias) {
    extern __shared__ float ps[];
    float* es = ps;                 /* e[k][c], swizzled, pad 132 */
    float* wsm = ps + 128 * PAD;    /* w[k][d], swizzled, pad 132 */
    const int tid = threadIdx.x;
    const int tx = tid & 15, ty = tid >> 4;
    const int c0 = blockIdx.x * 128;

#pragma unroll
    for (int i = 0; i < 16; i++) {
        int f = tid + i * 256;
        int row = f >> 5;
        int c4 = f & 31;
        int sw = (((row >> 2) ^ (c4 & 7)) << 2) | (row & 3);
        float4 v = *((const float4*)(emb + (size_t)(c0 + row) * DIM) + c4);
        es[(4 * c4 + 0) * PAD + sw] = v.x;
        es[(4 * c4 + 1) * PAD + sw] = v.y;
        es[(4 * c4 + 2) * PAD + sw] = v.z;
        es[(4 * c4 + 3) * PAD + sw] = v.w;
        float4 w = *((const float4*)(pw + (size_t)row * DIM) + c4);
        wsm[(4 * c4 + 0) * PAD + sw] = w.x;
        wsm[(4 * c4 + 1) * PAD + sw] = w.y;
        wsm[(4 * c4 + 2) * PAD + sw] = w.z;
        wsm[(4 * c4 + 3) * PAD + sw] = w.w;
    }
    __syncthreads();

    float acc[8][8];
#pragma unroll
    for (int im = 0; im < 8; im++)
#pragma unroll
        for (int jn = 0; jn < 8; jn++) acc[im][jn] = 0.0f;

#pragma unroll 4
    for (int k = 0; k < 128; k++) {
        int s = (k >> 2) & 7;
        const float* er = es + k * PAD;
        const float* wr = wsm + k * PAD;
        float4 a0 = *(const float4*)(er + ((ty ^ s) << 2));
        float4 a1 = *(const float4*)(er + 64 + ((ty ^ s) << 2));
        float4 b0 = *(const float4*)(wr + ((tx ^ s) << 2));
        float4 b1 = *(const float4*)(wr + 64 + ((tx ^ s) << 2));
        float a[8] = {a0.x, a0.y, a0.z, a0.w, a1.x, a1.y, a1.z, a1.w};
        float b[8] = {b0.x, b0.y, b0.z, b0.w, b1.x, b1.y, b1.z, b1.w};
#pragma unroll
        for (int im = 0; im < 8; im++)
#pragma unroll
            for (int jn = 0; jn < 8; jn++)
                acc[im][jn] = fmaf(a[im], b[jn], acc[im][jn]);
    }

    float cnp[8];
#pragma unroll
    for (int im = 0; im < 8; im++) cnp[im] = 0.0f;

#pragma unroll
    for (int im = 0; im < 8; im++) {
        int cl = (im < 4) ? (ty * 4 + im) : (64 + ty * 4 + im - 4);
        int cg = c0 + cl;
        int tile = cg >> 6, nblk = (cg >> 3) & 7, nl = cg & 7;
#pragma unroll
        for (int jn = 0; jn < 8; jn++) {
            int d = (jn < 4) ? (tx * 4 + jn) : (64 + tx * 4 + jn - 4);
            float val = acc[im][jn] + pbias[d];
            g_codebook[(size_t)cg * DIM + d] = val;
            cnp[im] = fmaf(val, val, cnp[im]);
            int kblk = d >> 4, kin = d & 15;
            int regsel = kin >> 3, ksub = (kin & 7) >> 1, par = kin & 1;
            int lane = nl * 4 + ksub;
            size_t off = (size_t)tile * TILE_BYTES + nblk * 2048 + kblk * 256
                       + lane * 8 + regsel * 4 + par * 2;
            *(__half*)(g_cbt + off) = __float2half_rn(val);
        }
    }
    /* reduce cnorm partials across the 16 tx lanes (half-warp) */
#pragma unroll
    for (int im = 0; im < 8; im++) {
#pragma unroll
        for (int o = 8; o > 0; o >>= 1)
            cnp[im] += __shfl_xor_sync(0xffffffffu, cnp[im], o, 16);
    }
    if (tx == 0) {
#pragma unroll
        for (int im = 0; im < 8; im++) {
            int cl = (im < 4) ? (ty * 4 + im) : (64 + ty * 4 + im - 4);
            g_cnorm[c0 + cl] = cnp[im];
        }
    }
}

/* ---------------- fused fp16 HMMA distance GEMM + top-4 argmin ---------------- */
__global__ __launch_bounds__(256, 2)
void k_gemm(const float* __restrict__ z) {
    extern __shared__ unsigned char smem[];
    const uint32_t sb = smem_u32(smem);
    const int tid = threadIdx.x;
    const int lane = tid & 31;
    const int warp = tid >> 5;
    const int r = lane >> 2;
    const int cc = lane & 3;
    const int m0 = blockIdx.x * BM;

    /* prefetch B tile 0 */
#pragma unroll
    for (int j = 0; j < 4; j++) {
        uint32_t off = (uint32_t)(tid + j * 256) * 16;
        CP16(sb + off, g_cbt + off);
    }
    CP_COMMIT();

    /* A fragments (fp16) in registers */
    uint32_t A[8][4];
    {
        const float* z0 = z + (size_t)(m0 + warp * 16 + r) * DIM;
#pragma unroll
        for (int kb = 0; kb < 8; kb++) {
#pragma unroll
            for (int q = 0; q < 4; q++) {
                const float* src = z0 + ((q & 1) ? 8 * DIM : 0) + kb * 16 + (q >> 1) * 8 + cc * 2;
                float2 v = *(const float2*)src;
                __half2 hh = __floats2half2_rn(v.x, v.y);
                A[kb][q] = *(uint32_t*)&hh;
            }
        }
    }

    /* top-4 state, rows a (r) and b (r+8) */
    float av0 = 3.4e38f, av1 = 3.4e38f, av2 = 3.4e38f, av3 = 3.4e38f;
    float bv0 = 3.4e38f, bv1 = 3.4e38f, bv2 = 3.4e38f, bv3 = 3.4e38f;
    int ai0 = 0, ai1 = 0, ai2 = 0, ai3 = 0;
    int bi0 = 0, bi1 = 0, bi2 = 0, bi3 = 0;

    for (int i = 0; i < ITERS; i++) {
        CP_WAIT0();
        __syncthreads();
        if (i + 1 < ITERS) {
            const unsigned char* src = g_cbt + (size_t)(i + 1) * TILE_BYTES;
            uint32_t dst = sb + ((i + 1) & 1) * TILE_BYTES;
#pragma unroll
            for (int j = 0; j < 4; j++) {
                uint32_t off = (uint32_t)(tid + j * 256) * 16;
                CP16(dst + off, src + off);
            }
            CP_COMMIT();
        }

        float acc[8][4];
#pragma unroll
        for (int nb = 0; nb < 8; nb++)
#pragma unroll
            for (int q = 0; q < 4; q++) acc[nb][q] = 0.0f;

        const uint32_t bbase = sb + (i & 1) * TILE_BYTES + lane * 8;
#pragma unroll
        for (int kb = 0; kb < 8; kb++) {
#pragma unroll
            for (int nb = 0; nb < 8; nb++) {
                uint32_t b0, b1;
                asm volatile("ld.shared.v2.b32 {%0,%1},[%2];"
                             : "=r"(b0), "=r"(b1) : "r"(bbase + nb * 2048 + kb * 256));
                MMA_F16(acc[nb], A[kb], b0, b1);
            }
        }

        const int n0i = i * 64;
#pragma unroll
        for (int nb = 0; nb < 8; nb++) {
            int n = n0i + nb * 8 + cc * 2;
            float2 cn = *(const float2*)(g_cnorm + n);
            float s0 = fmaf(-2.0f, acc[nb][0], cn.x);
            float s1 = fmaf(-2.0f, acc[nb][1], cn.y);
            float s2 = fmaf(-2.0f, acc[nb][2], cn.x);
            float s3 = fmaf(-2.0f, acc[nb][3], cn.y);
            INS4(av0, av1, av2, av3, ai0, ai1, ai2, ai3, s0, n);
            INS4(av0, av1, av2, av3, ai0, ai1, ai2, ai3, s1, n + 1);
            INS4(bv0, bv1, bv2, bv3, bi0, bi1, bi2, bi3, s2, n);
            INS4(bv0, bv1, bv2, bv3, bi0, bi1, bi2, bi3, s3, n + 1);
        }
    }

    /* merge top-4 across the 4 cc lanes: snapshot partner state, then insert */
#pragma unroll
    for (int off = 1; off <= 2; off <<= 1) {
        float wa0 = __shfl_xor_sync(0xffffffffu, av0, off);
        float wa1 = __shfl_xor_sync(0xffffffffu, av1, off);
        float wa2 = __shfl_xor_sync(0xffffffffu, av2, off);
        float wa3 = __shfl_xor_sync(0xffffffffu, av3, off);
        int ja0 = __shfl_xor_sync(0xffffffffu, ai0, off);
        int ja1 = __shfl_xor_sync(0xffffffffu, ai1, off);
        int ja2 = __shfl_xor_sync(0xffffffffu, ai2, off);
        int ja3 = __shfl_xor_sync(0xffffffffu, ai3, off);
        float wb0 = __shfl_xor_sync(0xffffffffu, bv0, off);
        float wb1 = __shfl_xor_sync(0xffffffffu, bv1, off);
        float wb2 = __shfl_xor_sync(0xffffffffu, bv2, off);
        float wb3 = __shfl_xor_sync(0xffffffffu, bv3, off);
        int jb0 = __shfl_xor_sync(0xffffffffu, bi0, off);
        int jb1 = __shfl_xor_sync(0xffffffffu, bi1, off);
        int jb2 = __shfl_xor_sync(0xffffffffu, bi2, off);
        int jb3 = __shfl_xor_sync(0xffffffffu, bi3, off);
        INS4(av0, av1, av2, av3, ai0, ai1, ai2, ai3, wa0, ja0);
        INS4(av0, av1, av2, av3, ai0, ai1, ai2, ai3, wa1, ja1);
        INS4(av0, av1, av2, av3, ai0, ai1, ai2, ai3, wa2, ja2);
        INS4(av0, av1, av2, av3, ai0, ai1, ai2, ai3, wa3, ja3);
        INS4(bv0, bv1, bv2, bv3, bi0, bi1, bi2, bi3, wb0, jb0);
        INS4(bv0, bv1, bv2, bv3, bi0, bi1, bi2, bi3, wb1, jb1);
        INS4(bv0, bv1, bv2, bv3, bi0, bi1, bi2, bi3, wb2, jb2);
        INS4(bv0, bv1, bv2, bv3, bi0, bi1, bi2, bi3, wb3, jb3);
    }
    if (cc == 0) {
        int tok = m0 + warp * 16 + r;
        g_cand[tok]     = make_int4(ai0, ai1, ai2, ai3);
        g_cand[tok + 8] = make_int4(bi0, bi1, bi2, bi3);
    }
}

/* ---------------- exact fp32 rescore of top-4 + gather + loss partials ---------------- */
__global__ __launch_bounds__(256)
void k_rescore(const float* __restrict__ z, float* __restrict__ out) {
    __shared__ float wsq[8];
    const int lane = threadIdx.x & 31;
    const int warp = threadIdx.x >> 5;
    const int t = blockIdx.x * 8 + warp;

    int4 cd = g_cand[t];
    float4 zv = ((const float4*)(z + (size_t)t * DIM))[lane];
    float4 c0 = ((const float4*)(g_codebook + (size_t)cd.x * DIM))[lane];
    float4 c1 = ((const float4*)(g_codebook + (size_t)cd.y * DIM))[lane];
    float4 c2 = ((const float4*)(g_codebook + (size_t)cd.z * DIM))[lane];
    float4 c3 = ((const float4*)(g_codebook + (size_t)cd.w * DIM))[lane];
    float d0 = zv.x * c0.x + zv.y * c0.y + zv.z * c0.z + zv.w * c0.w;
    float d1 = zv.x * c1.x + zv.y * c1.y + zv.z * c1.z + zv.w * c1.w;
    float d2 = zv.x * c2.x + zv.y * c2.y + zv.z * c2.z + zv.w * c2.w;
    float d3 = zv.x * c3.x + zv.y * c3.y + zv.z * c3.z + zv.w * c3.w;
#pragma unroll
    for (int o = 16; o > 0; o >>= 1) {
        d0 += __shfl_xor_sync(0xffffffffu, d0, o);
        d1 += __shfl_xor_sync(0xffffffffu, d1, o);
        d2 += __shfl_xor_sync(0xffffffffu, d2, o);
        d3 += __shfl_xor_sync(0xffffffffu, d3, o);
    }
    float s0 = g_cnorm[cd.x] - 2.0f * d0;
    float s1 = g_cnorm[cd.y] - 2.0f * d1;
    float s2 = g_cnorm[cd.z] - 2.0f * d2;
    float s3 = g_cnorm[cd.w] - 2.0f * d3;

    float bs = s0; int bi = cd.x; float4 c = c0;
    if (s1 < bs || (s1 == bs && cd.y < bi)) { bs = s1; bi = cd.y; c = c1; }
    if (s2 < bs || (s2 == bs && cd.z < bi)) { bs = s2; bi = cd.z; c = c2; }
    if (s3 < bs || (s3 == bs && cd.w < bi)) { bs = s3; bi = cd.w; c = c3; }

    float dx = c.x - zv.x, dy = c.y - zv.y, dz = c.z - zv.z, dw = c.w - zv.w;
    float4 o4;
    o4.x = zv.x + dx; o4.y = zv.y + dy; o4.z = zv.z + dz; o4.w = zv.w + dw;
    ((float4*)(out + (size_t)t * DIM))[lane] = o4;

    float sq = dx * dx + dy * dy + dz * dz + dw * dw;
#pragma unroll
    for (int o = 16; o > 0; o >>= 1) sq += __shfl_xor_sync(0xffffffffu, sq, o);
    if (lane == 0) {
        wsq[warp] = sq;
        atomicAdd(&g_counts[bi], 1);
    }
    __syncthreads();
    if (threadIdx.x == 0) {
        double s = 0.0;
#pragma unroll
        for (int i = 0; i < 8; i++) s += (double)wsq[i];
        g_ssep[blockIdx.x] = s;
    }
}

/* ---------------- finalize commit_loss + perplexity ---------------- */
__global__ void k_final(float* __restrict__ out) {
    __shared__ double wd[8];
    __shared__ float wf[8];
    double sd = 0.0;
    for (int j = threadIdx.x; j < T_TOK / 8; j += 256) sd += g_ssep[j];
    float s = 0.0f;
    const float invT = 1.0f / (float)T_TOK;
    for (int i = threadIdx.x; i < KC; i += 256) {
        float e = (float)g_counts[i] * invT;
        s += e * logf(e + 1e-8f);
    }
#pragma unroll
    for (int o = 16; o > 0; o >>= 1) {
        sd += __shfl_down_sync(0xffffffffu, sd, o);
        s  += __shfl_down_sync(0xffffffffu, s, o);
    }
    if ((threadIdx.x & 31) == 0) { wd[threadIdx.x >> 5] = sd; wf[threadIdx.x >> 5] = s; }
    __syncthreads();
    if (threadIdx.x == 0) {
        double td = 0.0; float tf = 0.0f;
#pragma unroll
        for (int i = 0; i < 8; i++) { td += wd[i]; tf += wf[i]; }
        double mse = td / (double)((size_t)T_TOK * DIM);
        out[(size_t)T_TOK * DIM]     = (float)(1.25 * mse);
        out[(size_t)T_TOK * DIM + 1] = expf(-tf);
    }
}

extern "C" void kernel_launch(void* const* d_in, const int* in_sizes, int n_in,
                              void* d_out, int out_size) {
    const float* z   = (const float*)d_in[0];
    const float* emb = (const float*)d_in[1];
    const float* pw  = (const float*)d_in[2];
    const float* pb  = (const float*)d_in[3];
    float* out = (float*)d_out;

    cudaFuncSetAttribute(k_proj, cudaFuncAttributeMaxDynamicSharedMemorySize, SMEM_PROJ);
    cudaFuncSetAttribute(k_gemm, cudaFuncAttributeMaxDynamicSharedMemorySize, SMEM_GEMM);

    k_init<<<KC / 256, 256>>>();
    k_proj<<<KC / 128, 256, SMEM_PROJ>>>(emb, pw, pb);
    k_gemm<<<GRID_GEMM, 256, SMEM_GEMM>>>(z);
    k_rescore<<<T_TOK / 8, 256>>>(z, out);
    k_final<<<1, 256>>>(out);
}